// round 3
// baseline (speedup 1.0000x reference)
#include <cuda_runtime.h>

#define NNODES 50000
#define NB 2
#define FDIM 128
#define EDGES_MAX 800000
#define M_TOTAL (NB * NNODES)   // 100000 rows

// Scratch: __device__ globals only (no allocations allowed)
__device__ int g_deg[NNODES];
__device__ int g_rowstart[NNODES + 1];
__device__ int g_cursor[NNODES];
__device__ int g_csr[EDGES_MAX];
__device__ float g_norm[(size_t)M_TOTAL * FDIM];   // normalized aggregation, 51.2MB

// ---------------------------------------------------------------------------
__global__ void k_zero() {
    int i = blockIdx.x * blockDim.x + threadIdx.x;
    if (i < NNODES) g_deg[i] = 0;
}

// edges is int32 [E,2] (JAX x64-disabled downgrades int64 -> int32)
__global__ void k_hist(const int* __restrict__ edges, int E) {
    int e = blockIdx.x * blockDim.x + threadIdx.x;
    if (e < E) {
        int dst = edges[2 * e + 1];
        atomicAdd(&g_deg[dst], 1);
    }
}

// single-block exclusive scan -> rowstart/cursor
__global__ void k_scan() {
    __shared__ int part[1024];
    int tid = threadIdx.x;
    const int chunk = (NNODES + 1023) / 1024;
    int start = tid * chunk;
    int end = start + chunk;
    if (end > NNODES) end = NNODES;
    if (start > NNODES) start = NNODES;
    int s = 0;
    for (int i = start; i < end; i++) s += g_deg[i];
    part[tid] = s;
    __syncthreads();
    for (int off = 1; off < 1024; off <<= 1) {
        int v = 0;
        if (tid >= off) v = part[tid - off];
        __syncthreads();
        if (tid >= off) part[tid] += v;
        __syncthreads();
    }
    int run = (tid == 0) ? 0 : part[tid - 1];
    for (int i = start; i < end; i++) {
        g_rowstart[i] = run;
        g_cursor[i] = run;
        run += g_deg[i];
    }
    if (tid == 1023) g_rowstart[NNODES] = part[1023];
}

__global__ void k_fill(const int* __restrict__ edges, int E) {
    int e = blockIdx.x * blockDim.x + threadIdx.x;
    if (e < E) {
        int src = edges[2 * e];
        int dst = edges[2 * e + 1];
        int pos = atomicAdd(&g_cursor[dst], 1);
        g_csr[pos] = src;
    }
}

// ---------------------------------------------------------------------------
// Aggregation: one warp per (b, node). Lane l owns features [4l, 4l+4).
// Gathers deg neighbors (512B coalesced per neighbor), normalizes by deg+1.
__global__ void __launch_bounds__(256)
k_agg(const float* __restrict__ nodes) {
    int wid = (blockIdx.x * blockDim.x + threadIdx.x) >> 5;
    int lane = threadIdx.x & 31;
    if (wid >= M_TOTAL) return;
    int b = wid / NNODES;
    int n = wid - b * NNODES;

    const int rs = g_rowstart[n];
    const int re = g_rowstart[n + 1];
    const float* nb = nodes + (size_t)b * NNODES * FDIM;

    float4 acc = make_float4(0.f, 0.f, 0.f, 0.f);
    int i = rs;
    // 2-deep manual pipeline for MLP
    for (; i + 2 <= re; i += 2) {
        int s0 = g_csr[i];
        int s1 = g_csr[i + 1];
        float4 v0 = *(const float4*)(nb + (size_t)s0 * FDIM + lane * 4);
        float4 v1 = *(const float4*)(nb + (size_t)s1 * FDIM + lane * 4);
        acc.x += v0.x + v1.x;
        acc.y += v0.y + v1.y;
        acc.z += v0.z + v1.z;
        acc.w += v0.w + v1.w;
    }
    if (i < re) {
        int s0 = g_csr[i];
        float4 v0 = *(const float4*)(nb + (size_t)s0 * FDIM + lane * 4);
        acc.x += v0.x; acc.y += v0.y; acc.z += v0.z; acc.w += v0.w;
    }
    const float scale = 1.0f / (float)(re - rs + 1);
    acc.x *= scale; acc.y *= scale; acc.z *= scale; acc.w *= scale;
    *(float4*)(&g_norm[(size_t)wid * FDIM + lane * 4]) = acc;
}

// ---------------------------------------------------------------------------
// GEMM: out[M,128] = relu(g_norm[M,128] @ W[128,128] + b)
// Block = 256 threads = 2 units of 128. Each unit owns 4 rows; thread owns
// output column `lane` for those 4 rows. W staged in shared in two 32KB
// halves; norm rows staged transposed (float4 broadcast per f).
#define GU 2
#define RPU 4
#define ROWS_PER_BLOCK (GU * RPU)   // 8

__global__ void __launch_bounds__(256)
k_gemm(const float* __restrict__ weight,
       const float* __restrict__ bias,
       float* __restrict__ out) {
    __shared__ float Ws[64 * FDIM];                 // 32KB: one k-half of W
    __shared__ float nshT[GU][FDIM * RPU];          // 4KB: [f][row] transposed

    const int tid = threadIdx.x;
    const int unit = tid >> 7;
    const int lane = tid & 127;
    const int row0 = blockIdx.x * ROWS_PER_BLOCK + unit * RPU;

    // Stage 4 norm rows, transposed: nshT[unit][f*4 + r]
    {
        const float* src = &g_norm[(size_t)row0 * FDIM];
        #pragma unroll
        for (int r = 0; r < RPU; r++) {
            float v = src[r * FDIM + lane];
            nshT[unit][lane * RPU + r] = v;
        }
    }

    const float bias_o = bias[lane];
    float a0 = bias_o, a1 = bias_o, a2 = bias_o, a3 = bias_o;

    #pragma unroll
    for (int kh = 0; kh < 2; kh++) {
        __syncthreads();
        // Cooperative load of W[kh*64 .. +64][0..128): 8192 floats / 256 thr
        {
            const float4* w4 = (const float4*)(weight + kh * 64 * FDIM);
            float4* s4 = (float4*)Ws;
            #pragma unroll
            for (int i = 0; i < 8; i++)
                s4[tid + i * 256] = w4[tid + i * 256];
        }
        __syncthreads();

        const float4* nf = (const float4*)&nshT[unit][kh * 64 * RPU];
        #pragma unroll 16
        for (int f = 0; f < 64; f++) {
            const float wv = Ws[f * FDIM + lane];
            const float4 nv = nf[f];      // broadcast across unit
            a0 = fmaf(wv, nv.x, a0);
            a1 = fmaf(wv, nv.y, a1);
            a2 = fmaf(wv, nv.z, a2);
            a3 = fmaf(wv, nv.w, a3);
        }
    }

    float* o = out + (size_t)row0 * FDIM + lane;
    o[0 * FDIM] = fmaxf(a0, 0.0f);
    o[1 * FDIM] = fmaxf(a1, 0.0f);
    o[2 * FDIM] = fmaxf(a2, 0.0f);
    o[3 * FDIM] = fmaxf(a3, 0.0f);
}

// ---------------------------------------------------------------------------
extern "C" void kernel_launch(void* const* d_in, const int* in_sizes, int n_in,
                              void* d_out, int out_size) {
    const float* nodes = (const float*)d_in[0];
    const int* edges = (const int*)d_in[1];      // int32 [E,2]
    const float* weight = (const float*)d_in[2];
    const float* bias = (const float*)d_in[3];
    float* out = (float*)d_out;

    int E = in_sizes[1] / 2;
    if (E > EDGES_MAX) E = EDGES_MAX;

    k_zero<<<(NNODES + 255) / 256, 256>>>();
    k_hist<<<(E + 255) / 256, 256>>>(edges, E);
    k_scan<<<1, 1024>>>();
    k_fill<<<(E + 255) / 256, 256>>>(edges, E);

    // one warp per (b,node): 100000 warps / 8 warps per block
    k_agg<<<(M_TOTAL * 32 + 255) / 256, 256>>>(nodes);

    // 100000 rows / 8 rows per block
    k_gemm<<<M_TOTAL / ROWS_PER_BLOCK, 256>>>(weight, bias, out);
}

// round 4
// speedup vs baseline: 1.3241x; 1.3241x over previous
#include <cuda_runtime.h>

#define NNODES 50000
#define NB 2
#define FDIM 128
#define EDGES_MAX 800000
#define M_TOTAL (NB * NNODES)          // 100000 rows
#define ROWS_PB 64
#define NBLOCKS ((M_TOTAL + ROWS_PB - 1) / ROWS_PB)   // 1563

// Scratch: __device__ globals only (no allocations allowed)
__device__ int g_deg[NNODES];
__device__ int g_rowstart[NNODES + 1];
__device__ int g_cursor[NNODES];
__device__ int g_csr[EDGES_MAX];

// ---------------------------------------------------------------------------
__global__ void k_zero() {
    int i = blockIdx.x * blockDim.x + threadIdx.x;
    if (i < NNODES) g_deg[i] = 0;
}

// edges is int32 [E,2]
__global__ void k_hist(const int2* __restrict__ edges, int E) {
    int e = blockIdx.x * blockDim.x + threadIdx.x;
    if (e < E) atomicAdd(&g_deg[edges[e].y], 1);
}

// single-block exclusive scan -> rowstart/cursor
__global__ void k_scan() {
    __shared__ int part[1024];
    int tid = threadIdx.x;
    const int chunk = (NNODES + 1023) / 1024;
    int start = tid * chunk;
    int end = start + chunk;
    if (end > NNODES) end = NNODES;
    if (start > NNODES) start = NNODES;
    int s = 0;
    for (int i = start; i < end; i++) s += g_deg[i];
    part[tid] = s;
    __syncthreads();
    for (int off = 1; off < 1024; off <<= 1) {
        int v = 0;
        if (tid >= off) v = part[tid - off];
        __syncthreads();
        if (tid >= off) part[tid] += v;
        __syncthreads();
    }
    int run = (tid == 0) ? 0 : part[tid - 1];
    for (int i = start; i < end; i++) {
        g_rowstart[i] = run;
        g_cursor[i] = run;
        run += g_deg[i];
    }
    if (tid == 1023) g_rowstart[NNODES] = part[1023];
}

__global__ void k_fill(const int2* __restrict__ edges, int E) {
    int e = blockIdx.x * blockDim.x + threadIdx.x;
    if (e < E) {
        int2 ed = edges[e];
        int pos = atomicAdd(&g_cursor[ed.y], 1);
        g_csr[pos] = ed.x;
    }
}

// ---------------------------------------------------------------------------
// Packed f32x2 helpers (sm_103a FFMA2 path — ptxas won't auto-fuse)
__device__ __forceinline__ unsigned long long pack2(float x, float y) {
    unsigned long long r;
    asm("mov.b64 %0, {%1, %2};" : "=l"(r) : "f"(x), "f"(y));
    return r;
}
__device__ __forceinline__ void unpack2(unsigned long long v, float& x, float& y) {
    asm("mov.b64 {%0, %1}, %2;" : "=f"(x), "=f"(y) : "l"(v));
}
__device__ __forceinline__ void fma2(unsigned long long& d,
                                     unsigned long long a,
                                     unsigned long long b) {
    asm("fma.rn.f32x2 %0, %1, %2, %0;" : "+l"(d) : "l"(a), "l"(b));
}

// ---------------------------------------------------------------------------
// Fused: aggregate 64 rows into smem, then GEMM(64x128x128)+bias+relu.
// Phase 1: warp per node (8 nodes/warp), lane owns 4 features, gathers
//          deg coalesced float4 rows, normalizes, writes As[row][128].
// Phase 2: thread owns 4 output cols x 8 rows; W staged in 4x16KB k-quarters;
//          accumulators packed over column pairs -> FFMA2 (2 FMA/instr).
__global__ void __launch_bounds__(256)
k_fused(const float* __restrict__ nodes,
        const float* __restrict__ weight,
        const float* __restrict__ bias,
        float* __restrict__ out) {
    __shared__ float As[ROWS_PB][FDIM];   // 32KB
    __shared__ float Ws[32][FDIM];        // 16KB  (one k-quarter of W)

    const int tid = threadIdx.x;
    const int w = tid >> 5;
    const int lane = tid & 31;
    const int row0 = blockIdx.x * ROWS_PB;

    // ---- phase 1: aggregation ----
    #pragma unroll 1
    for (int j = 0; j < 8; j++) {
        const int rl = w * 8 + j;
        const int row = row0 + rl;
        float4 acc = make_float4(0.f, 0.f, 0.f, 0.f);
        float scale = 1.0f;
        if (row < M_TOTAL) {
            const int b = row / NNODES;
            const int n = row - b * NNODES;
            const int rs = g_rowstart[n];
            const int re = g_rowstart[n + 1];
            const float* nb = nodes + (size_t)b * NNODES * FDIM + lane * 4;
            int i = rs;
            for (; i + 4 <= re; i += 4) {      // 4-deep MLP
                int s0 = g_csr[i], s1 = g_csr[i + 1];
                int s2 = g_csr[i + 2], s3 = g_csr[i + 3];
                float4 v0 = *(const float4*)(nb + (size_t)s0 * FDIM);
                float4 v1 = *(const float4*)(nb + (size_t)s1 * FDIM);
                float4 v2 = *(const float4*)(nb + (size_t)s2 * FDIM);
                float4 v3 = *(const float4*)(nb + (size_t)s3 * FDIM);
                acc.x += (v0.x + v1.x) + (v2.x + v3.x);
                acc.y += (v0.y + v1.y) + (v2.y + v3.y);
                acc.z += (v0.z + v1.z) + (v2.z + v3.z);
                acc.w += (v0.w + v1.w) + (v2.w + v3.w);
            }
            for (; i < re; i++) {
                int s0 = g_csr[i];
                float4 v0 = *(const float4*)(nb + (size_t)s0 * FDIM);
                acc.x += v0.x; acc.y += v0.y; acc.z += v0.z; acc.w += v0.w;
            }
            scale = 1.0f / (float)(re - rs + 1);
        }
        *(float4*)&As[rl][lane * 4] =
            make_float4(acc.x * scale, acc.y * scale, acc.z * scale, acc.w * scale);
    }

    // ---- phase 2: GEMM ----
    const int colg = tid & 31;    // cols 4*colg .. +4
    const int rowg = tid >> 5;    // rows 8*rowg .. +8

    const float4 b4 = *(const float4*)(bias + colg * 4);
    unsigned long long a01[8], a23[8];
    #pragma unroll
    for (int r = 0; r < 8; r++) {
        a01[r] = pack2(b4.x, b4.y);
        a23[r] = pack2(b4.z, b4.w);
    }

    const float4* w4g = (const float4*)weight;
    #pragma unroll
    for (int kq = 0; kq < 4; kq++) {
        __syncthreads();   // kq=0: As ready; kq>0: Ws reads done
        #pragma unroll
        for (int i = 0; i < 4; i++)
            ((float4*)Ws)[tid + i * 256] = w4g[kq * 1024 + tid + i * 256];
        __syncthreads();

        #pragma unroll 4
        for (int k = 0; k < 32; k++) {
            const unsigned long long w01 =
                *(const unsigned long long*)&Ws[k][colg * 4];
            const unsigned long long w23 =
                *(const unsigned long long*)&Ws[k][colg * 4 + 2];
            const float* arow = &As[rowg * 8][kq * 32 + k];
            #pragma unroll
            for (int r = 0; r < 8; r++) {
                const float a = arow[r * FDIM];   // broadcast LDS
                const unsigned long long ap = pack2(a, a);
                fma2(a01[r], w01, ap);
                fma2(a23[r], w23, ap);
            }
        }
    }

    // ---- store with relu ----
    #pragma unroll
    for (int r = 0; r < 8; r++) {
        const int row = row0 + rowg * 8 + r;
        if (row < M_TOTAL) {
            float x, y, z, u;
            unpack2(a01[r], x, y);
            unpack2(a23[r], z, u);
            float4 o = make_float4(fmaxf(x, 0.f), fmaxf(y, 0.f),
                                   fmaxf(z, 0.f), fmaxf(u, 0.f));
            *(float4*)(out + (size_t)row * FDIM + colg * 4) = o;
        }
    }
}

// ---------------------------------------------------------------------------
extern "C" void kernel_launch(void* const* d_in, const int* in_sizes, int n_in,
                              void* d_out, int out_size) {
    const float* nodes = (const float*)d_in[0];
    const int2* edges = (const int2*)d_in[1];    // int32 [E,2]
    const float* weight = (const float*)d_in[2];
    const float* bias = (const float*)d_in[3];
    float* out = (float*)d_out;

    int E = in_sizes[1] / 2;
    if (E > EDGES_MAX) E = EDGES_MAX;

    k_zero<<<(NNODES + 255) / 256, 256>>>();
    k_hist<<<(E + 255) / 256, 256>>>(edges, E);
    k_scan<<<1, 1024>>>();
    k_fill<<<(E + 255) / 256, 256>>>(edges, E);
    k_fused<<<NBLOCKS, 256>>>(nodes, weight, bias, out);
}

// round 5
// speedup vs baseline: 1.4639x; 1.1055x over previous
#include <cuda_runtime.h>

#define NNODES 50000
#define NB 2
#define FDIM 128
#define EDGES_MAX 800000
#define M_TOTAL (NB * NNODES)          // 100000 rows
#define ROWS_PB 64
#define NBLOCKS ((M_TOTAL + ROWS_PB - 1) / ROWS_PB)   // 1563

// Scratch: __device__ globals only (no allocations allowed)
__device__ int g_deg[NNODES];
__device__ int g_rowstart[NNODES + 1];
__device__ int g_cursor[NNODES];
__device__ int g_csr[EDGES_MAX];

// ---------------------------------------------------------------------------
__global__ void k_zero() {
    int i = blockIdx.x * blockDim.x + threadIdx.x;
    if (i < NNODES) g_deg[i] = 0;
}

// edges is int32 [E,2]; int4 = 2 edges per thread (deeper MLP on the
// latency-bound edge pass)
__global__ void k_hist(const int4* __restrict__ edges2, int Epairs) {
    int i = blockIdx.x * blockDim.x + threadIdx.x;
    if (i < Epairs) {
        int4 e2 = edges2[i];
        atomicAdd(&g_deg[e2.y], 1);    // REDG (result unused)
        atomicAdd(&g_deg[e2.w], 1);
    }
}

// single-block exclusive scan -> rowstart/cursor
__global__ void k_scan() {
    __shared__ int part[1024];
    int tid = threadIdx.x;
    const int chunk = (NNODES + 1023) / 1024;
    int start = tid * chunk;
    int end = start + chunk;
    if (end > NNODES) end = NNODES;
    if (start > NNODES) start = NNODES;
    int s = 0;
    for (int i = start; i < end; i++) s += g_deg[i];
    part[tid] = s;
    __syncthreads();
    for (int off = 1; off < 1024; off <<= 1) {
        int v = 0;
        if (tid >= off) v = part[tid - off];
        __syncthreads();
        if (tid >= off) part[tid] += v;
        __syncthreads();
    }
    int run = (tid == 0) ? 0 : part[tid - 1];
    for (int i = start; i < end; i++) {
        g_rowstart[i] = run;
        g_cursor[i] = run;
        run += g_deg[i];
    }
    if (tid == 1023) g_rowstart[NNODES] = part[1023];
}

__global__ void k_fill(const int4* __restrict__ edges2, int Epairs) {
    int i = blockIdx.x * blockDim.x + threadIdx.x;
    if (i < Epairs) {
        int4 e2 = edges2[i];
        int p0 = atomicAdd(&g_cursor[e2.y], 1);
        g_csr[p0] = e2.x;
        int p1 = atomicAdd(&g_cursor[e2.w], 1);
        g_csr[p1] = e2.z;
    }
}

// ---------------------------------------------------------------------------
// Packed f32x2 helpers (sm_103a FFMA2 path — ptxas won't auto-fuse)
__device__ __forceinline__ unsigned long long pack2(float x, float y) {
    unsigned long long r;
    asm("mov.b64 %0, {%1, %2};" : "=l"(r) : "f"(x), "f"(y));
    return r;
}
__device__ __forceinline__ void unpack2(unsigned long long v, float& x, float& y) {
    asm("mov.b64 {%0, %1}, %2;" : "=f"(x), "=f"(y) : "l"(v));
}
__device__ __forceinline__ void fma2(unsigned long long& d,
                                     unsigned long long a,
                                     unsigned long long b) {
    asm("fma.rn.f32x2 %0, %1, %2, %0;" : "+l"(d) : "l"(a), "l"(b));
}

// ---------------------------------------------------------------------------
// Fused: aggregate 64 rows into smem, then GEMM(64x128x128)+bias+relu.
// Phase 1: warp per node (8 nodes/warp), lane owns 4 features, gathers
//          deg coalesced float4 rows, normalizes, writes As[row][128].
// Phase 2: thread owns 4 output cols x 8 rows; W staged in 4x16KB k-quarters.
//          k tiled by 4: A loaded as broadcast LDS.128 (4 ks per row),
//          W loaded as LDS.128 -> ulonglong2 (two packed FFMA2 operands).
//          FFMA2-pipe-bound (~128 pipe-cyc per k4 per SMSP vs ~24 smem phases).
__global__ void __launch_bounds__(256, 3)
k_fused(const float* __restrict__ nodes,
        const float* __restrict__ weight,
        const float* __restrict__ bias,
        float* __restrict__ out) {
    __shared__ float As[ROWS_PB][FDIM];   // 32KB
    __shared__ float Ws[32][FDIM];        // 16KB  (one k-quarter of W)

    const int tid = threadIdx.x;
    const int w = tid >> 5;
    const int lane = tid & 31;
    const int row0 = blockIdx.x * ROWS_PB;

    // ---- phase 1: aggregation ----
    #pragma unroll 1
    for (int j = 0; j < 8; j++) {
        const int rl = w * 8 + j;
        const int row = row0 + rl;
        float4 acc = make_float4(0.f, 0.f, 0.f, 0.f);
        float scale = 1.0f;
        if (row < M_TOTAL) {
            const int b = row / NNODES;
            const int n = row - b * NNODES;
            const int rs = g_rowstart[n];
            const int re = g_rowstart[n + 1];
            const float* nb = nodes + (size_t)b * NNODES * FDIM + lane * 4;
            int i = rs;
            for (; i + 4 <= re; i += 4) {      // 4-deep MLP
                int s0 = g_csr[i], s1 = g_csr[i + 1];
                int s2 = g_csr[i + 2], s3 = g_csr[i + 3];
                float4 v0 = *(const float4*)(nb + (size_t)s0 * FDIM);
                float4 v1 = *(const float4*)(nb + (size_t)s1 * FDIM);
                float4 v2 = *(const float4*)(nb + (size_t)s2 * FDIM);
                float4 v3 = *(const float4*)(nb + (size_t)s3 * FDIM);
                acc.x += (v0.x + v1.x) + (v2.x + v3.x);
                acc.y += (v0.y + v1.y) + (v2.y + v3.y);
                acc.z += (v0.z + v1.z) + (v2.z + v3.z);
                acc.w += (v0.w + v1.w) + (v2.w + v3.w);
            }
            for (; i < re; i++) {
                int s0 = g_csr[i];
                float4 v0 = *(const float4*)(nb + (size_t)s0 * FDIM);
                acc.x += v0.x; acc.y += v0.y; acc.z += v0.z; acc.w += v0.w;
            }
            scale = 1.0f / (float)(re - rs + 1);
        }
        *(float4*)&As[rl][lane * 4] =
            make_float4(acc.x * scale, acc.y * scale, acc.z * scale, acc.w * scale);
    }

    // ---- phase 2: GEMM ----
    const int colg = tid & 31;    // cols 4*colg .. +4
    const int rowg = tid >> 5;    // rows 8*rowg .. +8 (all lanes of warp: same)

    const float4 b4 = *(const float4*)(bias + colg * 4);
    unsigned long long a01[8], a23[8];
    #pragma unroll
    for (int r = 0; r < 8; r++) {
        a01[r] = pack2(b4.x, b4.y);
        a23[r] = pack2(b4.z, b4.w);
    }

    const float4* w4g = (const float4*)weight;
    #pragma unroll
    for (int kq = 0; kq < 4; kq++) {
        __syncthreads();   // kq=0: As ready; kq>0: prior Ws reads done
        #pragma unroll
        for (int i = 0; i < 4; i++)
            ((float4*)Ws)[tid + i * 256] = w4g[kq * 1024 + tid + i * 256];
        __syncthreads();

        #pragma unroll
        for (int k4 = 0; k4 < 8; k4++) {
            // A: 4 k-values per row, broadcast across the warp (1 phase each)
            float4 areg[8];
            #pragma unroll
            for (int r = 0; r < 8; r++)
                areg[r] = *(const float4*)&As[rowg * 8 + r][kq * 32 + k4 * 4];

            #pragma unroll
            for (int kk = 0; kk < 4; kk++) {
                const ulonglong2 wv =
                    *(const ulonglong2*)&Ws[k4 * 4 + kk][colg * 4];
                #pragma unroll
                for (int r = 0; r < 8; r++) {
                    const float a = (kk == 0) ? areg[r].x :
                                    (kk == 1) ? areg[r].y :
                                    (kk == 2) ? areg[r].z : areg[r].w;
                    const unsigned long long ap = pack2(a, a);
                    fma2(a01[r], wv.x, ap);
                    fma2(a23[r], wv.y, ap);
                }
            }
        }
    }

    // ---- store with relu ----
    #pragma unroll
    for (int r = 0; r < 8; r++) {
        const int row = row0 + rowg * 8 + r;
        if (row < M_TOTAL) {
            float x, y, z, u;
            unpack2(a01[r], x, y);
            unpack2(a23[r], z, u);
            float4 o = make_float4(fmaxf(x, 0.f), fmaxf(y, 0.f),
                                   fmaxf(z, 0.f), fmaxf(u, 0.f));
            *(float4*)(out + (size_t)row * FDIM + colg * 4) = o;
        }
    }
}

// ---------------------------------------------------------------------------
extern "C" void kernel_launch(void* const* d_in, const int* in_sizes, int n_in,
                              void* d_out, int out_size) {
    const float* nodes = (const float*)d_in[0];
    const int4* edges2 = (const int4*)d_in[1];   // int32 [E,2], 2 edges per int4
    const float* weight = (const float*)d_in[2];
    const float* bias = (const float*)d_in[3];
    float* out = (float*)d_out;

    int E = in_sizes[1] / 2;
    if (E > EDGES_MAX) E = EDGES_MAX;
    int Epairs = E / 2;   // E is even (800000)

    k_zero<<<(NNODES + 255) / 256, 256>>>();
    k_hist<<<(Epairs + 255) / 256, 256>>>(edges2, Epairs);
    k_scan<<<1, 1024>>>();
    k_fill<<<(Epairs + 255) / 256, 256>>>(edges2, Epairs);
    k_fused<<<NBLOCKS, 256>>>(nodes, weight, bias, out);
}

// round 6
// speedup vs baseline: 1.5067x; 1.0292x over previous
#include <cuda_runtime.h>

#define NNODES 50000
#define NB 2
#define FDIM 128
#define EDGES_MAX 800000
#define M_TOTAL (NB * NNODES)
#define NODES_PB 32
#define NBLOCKS ((NNODES + NODES_PB - 1) / NODES_PB)   // 1563

// Scratch: __device__ globals only (zero-initialized at module load;
// k_scan re-zeros g_deg every call so replays see the same state)
__device__ int g_deg[NNODES];
__device__ int g_rowstart[NNODES + 1];
__device__ int g_cursor[NNODES];
__device__ int g_csr[EDGES_MAX];

// ---------------------------------------------------------------------------
// edges int32 [E,2]; int4 = 2 edges per thread
__global__ void k_hist(const int4* __restrict__ edges2, int Epairs) {
    int i = blockIdx.x * blockDim.x + threadIdx.x;
    if (i < Epairs) {
        int4 e2 = edges2[i];
        atomicAdd(&g_deg[e2.y], 1);
        atomicAdd(&g_deg[e2.w], 1);
    }
}

// single-block exclusive scan -> rowstart/cursor; self-clears g_deg
__global__ void k_scan() {
    __shared__ int part[1024];
    int tid = threadIdx.x;
    const int chunk = (NNODES + 1023) / 1024;
    int start = tid * chunk;
    int end = start + chunk;
    if (end > NNODES) end = NNODES;
    if (start > NNODES) start = NNODES;
    int s = 0;
    for (int i = start; i < end; i++) s += g_deg[i];
    part[tid] = s;
    __syncthreads();
    for (int off = 1; off < 1024; off <<= 1) {
        int v = 0;
        if (tid >= off) v = part[tid - off];
        __syncthreads();
        if (tid >= off) part[tid] += v;
        __syncthreads();
    }
    int run = (tid == 0) ? 0 : part[tid - 1];
    for (int i = start; i < end; i++) {
        int d = g_deg[i];
        g_rowstart[i] = run;
        g_cursor[i] = run;
        run += d;
        g_deg[i] = 0;          // ready for next replay
    }
    if (tid == 1023) g_rowstart[NNODES] = part[1023];
}

__global__ void k_fill(const int4* __restrict__ edges2, int Epairs) {
    int i = blockIdx.x * blockDim.x + threadIdx.x;
    if (i < Epairs) {
        int4 e2 = edges2[i];
        int p0 = atomicAdd(&g_cursor[e2.y], 1);
        g_csr[p0] = e2.x;
        int p1 = atomicAdd(&g_cursor[e2.w], 1);
        g_csr[p1] = e2.z;
    }
}

// ---------------------------------------------------------------------------
// Packed f32x2 helpers (FFMA2 path — ptxas won't auto-fuse)
__device__ __forceinline__ unsigned long long pack2(float x, float y) {
    unsigned long long r;
    asm("mov.b64 %0, {%1, %2};" : "=l"(r) : "f"(x), "f"(y));
    return r;
}
__device__ __forceinline__ void unpack2(unsigned long long v, float& x, float& y) {
    asm("mov.b64 {%0, %1}, %2;" : "=f"(x), "=f"(y) : "l"(v));
}
__device__ __forceinline__ void fma2(unsigned long long& d,
                                     unsigned long long a,
                                     unsigned long long b) {
    asm("fma.rn.f32x2 %0, %1, %2, %0;" : "+l"(d) : "l"(a), "l"(b));
}

// ---------------------------------------------------------------------------
// Fused: aggregate 32 nodes x BOTH batches into smem (batch-packed float2),
// then GEMM(64x128x128)+bias+relu with batch-packed FFMA2 accumulators.
//
// Phase 1: warp owns 4 nodes; lane owns 4 features; gathers deg neighbors for
//          batch0 AND batch1 (same CSR -> csr/rowstart traffic halved, MLP=4).
//          Writes As2[node][k] = {b0, b1}.
// Phase 2: thread owns 4 cols x 4 nodes, accumulator packed over batch.
//          A operand = direct LDS.64 of As2 (already a packed multiplier,
//          no MOV dup). Only W scalars dup'd (4 packs/k, serve 4 nodes).
//          ~29 issues per 32 FMA-pipe cycles per k -> FFMA2-pipe-bound.
__global__ void __launch_bounds__(256, 3)
k_fused(const float* __restrict__ nodes,
        const float* __restrict__ weight,
        const float* __restrict__ bias,
        float* __restrict__ out) {
    __shared__ float2 As2[NODES_PB][FDIM];   // 32KB {batch0, batch1}
    __shared__ float Ws[32][FDIM];           // 16KB (one k-quarter of W)

    const int tid = threadIdx.x;
    const int w = tid >> 5;
    const int lane = tid & 31;
    const int node0 = blockIdx.x * NODES_PB;

    // ---- phase 1: aggregation (both batches) ----
    #pragma unroll 1
    for (int j = 0; j < 4; j++) {
        const int nl = w * 4 + j;            // local node 0..31
        const int n = node0 + nl;
        float4 acc0 = make_float4(0.f, 0.f, 0.f, 0.f);
        float4 acc1 = make_float4(0.f, 0.f, 0.f, 0.f);
        float scale = 0.0f;
        if (n < NNODES) {
            const int rs = g_rowstart[n];
            const int re = g_rowstart[n + 1];
            const float* nb0 = nodes + lane * 4;
            const float* nb1 = nodes + (size_t)NNODES * FDIM + lane * 4;
            int i = rs;
            for (; i + 2 <= re; i += 2) {
                int s0 = g_csr[i], s1 = g_csr[i + 1];
                float4 a = *(const float4*)(nb0 + (size_t)s0 * FDIM);
                float4 b = *(const float4*)(nb0 + (size_t)s1 * FDIM);
                float4 c = *(const float4*)(nb1 + (size_t)s0 * FDIM);
                float4 d = *(const float4*)(nb1 + (size_t)s1 * FDIM);
                acc0.x += a.x + b.x; acc0.y += a.y + b.y;
                acc0.z += a.z + b.z; acc0.w += a.w + b.w;
                acc1.x += c.x + d.x; acc1.y += c.y + d.y;
                acc1.z += c.z + d.z; acc1.w += c.w + d.w;
            }
            if (i < re) {
                int s0 = g_csr[i];
                float4 a = *(const float4*)(nb0 + (size_t)s0 * FDIM);
                float4 c = *(const float4*)(nb1 + (size_t)s0 * FDIM);
                acc0.x += a.x; acc0.y += a.y; acc0.z += a.z; acc0.w += a.w;
                acc1.x += c.x; acc1.y += c.y; acc1.z += c.z; acc1.w += c.w;
            }
            scale = 1.0f / (float)(re - rs + 1);
        }
        // interleaved {b0,b1} per k
        float4 lo = make_float4(acc0.x * scale, acc1.x * scale,
                                acc0.y * scale, acc1.y * scale);
        float4 hi = make_float4(acc0.z * scale, acc1.z * scale,
                                acc0.w * scale, acc1.w * scale);
        *(float4*)&As2[nl][lane * 4] = lo;
        *(float4*)&As2[nl][lane * 4 + 2] = hi;
    }

    // ---- phase 2: GEMM ----
    const int colg = tid & 31;    // cols 4*colg .. +4
    const int nodeg = tid >> 5;   // local nodes 4*nodeg .. +4

    const float4 b4 = *(const float4*)(bias + colg * 4);
    unsigned long long acc[4][4];   // [node][col], packed {b0,b1}
    #pragma unroll
    for (int j = 0; j < 4; j++) {
        acc[j][0] = pack2(b4.x, b4.x);
        acc[j][1] = pack2(b4.y, b4.y);
        acc[j][2] = pack2(b4.z, b4.z);
        acc[j][3] = pack2(b4.w, b4.w);
    }

    const float4* w4g = (const float4*)weight;
    #pragma unroll
    for (int kq = 0; kq < 4; kq++) {
        __syncthreads();   // kq=0: As2 ready; kq>0: prior Ws reads done
        #pragma unroll
        for (int i = 0; i < 4; i++)
            ((float4*)Ws)[tid + i * 256] = w4g[kq * 1024 + tid + i * 256];
        __syncthreads();

        #pragma unroll 4
        for (int k = 0; k < 32; k++) {
            const float4 wv = *(const float4*)&Ws[k][colg * 4];
            const unsigned long long w0 = pack2(wv.x, wv.x);
            const unsigned long long w1 = pack2(wv.y, wv.y);
            const unsigned long long w2 = pack2(wv.z, wv.z);
            const unsigned long long w3 = pack2(wv.w, wv.w);
            #pragma unroll
            for (int j = 0; j < 4; j++) {
                const unsigned long long ap =
                    *(const unsigned long long*)&As2[nodeg * 4 + j][kq * 32 + k];
                fma2(acc[j][0], w0, ap);
                fma2(acc[j][1], w1, ap);
                fma2(acc[j][2], w2, ap);
                fma2(acc[j][3], w3, ap);
            }
        }
    }

    // ---- store with relu (unpack batch lanes) ----
    #pragma unroll
    for (int j = 0; j < 4; j++) {
        const int n = node0 + nodeg * 4 + j;
        if (n < NNODES) {
            float x0, y0, x1, y1, x2, y2, x3, y3;
            unpack2(acc[j][0], x0, y0);
            unpack2(acc[j][1], x1, y1);
            unpack2(acc[j][2], x2, y2);
            unpack2(acc[j][3], x3, y3);
            float4 o0 = make_float4(fmaxf(x0, 0.f), fmaxf(x1, 0.f),
                                    fmaxf(x2, 0.f), fmaxf(x3, 0.f));
            float4 o1 = make_float4(fmaxf(y0, 0.f), fmaxf(y1, 0.f),
                                    fmaxf(y2, 0.f), fmaxf(y3, 0.f));
            *(float4*)(out + (size_t)n * FDIM + colg * 4) = o0;
            *(float4*)(out + (size_t)(NNODES + n) * FDIM + colg * 4) = o1;
        }
    }
}

// ---------------------------------------------------------------------------
extern "C" void kernel_launch(void* const* d_in, const int* in_sizes, int n_in,
                              void* d_out, int out_size) {
    const float* nodes = (const float*)d_in[0];
    const int4* edges2 = (const int4*)d_in[1];   // int32 [E,2], 2 edges per int4
    const float* weight = (const float*)d_in[2];
    const float* bias = (const float*)d_in[3];
    float* out = (float*)d_out;

    int E = in_sizes[1] / 2;
    if (E > EDGES_MAX) E = EDGES_MAX;
    int Epairs = E / 2;   // E is even

    k_hist<<<(Epairs + 255) / 256, 256>>>(edges2, Epairs);
    k_scan<<<1, 1024>>>();
    k_fill<<<(Epairs + 255) / 256, 256>>>(edges2, Epairs);
    k_fused<<<NBLOCKS, 256>>>(nodes, weight, bias, out);
}

// round 7
// speedup vs baseline: 2.4800x; 1.6460x over previous
#include <cuda_runtime.h>

#define NNODES 50000
#define NB 2
#define FDIM 128
#define EDGES_MAX 800000
#define NODES_PB 32
#define NBLOCKS ((NNODES + NODES_PB - 1) / NODES_PB)   // 1563
#define SCAN_BLOCKS ((NNODES + 255) / 256)             // 196

// Scratch: __device__ globals only (zero-initialized at module load; the
// scan pipeline self-clears g_deg each call so graph replays are identical)
__device__ int g_deg[NNODES];
__device__ int g_rowstart[NNODES + 1];
__device__ int g_cursor[NNODES];
__device__ int g_exloc[NNODES];        // block-local exclusive scan temp
__device__ int g_bsum[SCAN_BLOCKS];
__device__ int g_csr[EDGES_MAX];

// ---------------------------------------------------------------------------
// edges int32 [E,2]; int4 = 2 edges per thread
__global__ void k_hist(const int4* __restrict__ edges2, int Epairs) {
    int i = blockIdx.x * blockDim.x + threadIdx.x;
    if (i < Epairs) {
        int4 e2 = edges2[i];
        atomicAdd(&g_deg[e2.y], 1);
        atomicAdd(&g_deg[e2.w], 1);
    }
}

// ---- hierarchical coalesced scan ----
// A: per-block exclusive scan of g_deg (coalesced), block sums to g_bsum
__global__ void __launch_bounds__(256)
k_scan_local() {
    __shared__ int wsum[8];
    const int tid = threadIdx.x;
    const int i = blockIdx.x * 256 + tid;
    const int lane = tid & 31;
    const int wrp = tid >> 5;

    int val = (i < NNODES) ? g_deg[i] : 0;

    // warp inclusive scan
    int incl = val;
    #pragma unroll
    for (int off = 1; off < 32; off <<= 1) {
        int v = __shfl_up_sync(0xffffffffu, incl, off);
        if (lane >= off) incl += v;
    }
    if (lane == 31) wsum[wrp] = incl;
    __syncthreads();
    if (wrp == 0) {
        int s = (lane < 8) ? wsum[lane] : 0;
        #pragma unroll
        for (int off = 1; off < 8; off <<= 1) {
            int v = __shfl_up_sync(0xffffffffu, s, off);
            if (lane >= off) s += v;
        }
        if (lane < 8) wsum[lane] = s;     // inclusive warp sums
    }
    __syncthreads();

    const int warpOff = (wrp == 0) ? 0 : wsum[wrp - 1];
    const int ex = warpOff + incl - val;  // block-local exclusive
    if (i < NNODES) g_exloc[i] = ex;
    if (tid == 255) g_bsum[blockIdx.x] = warpOff + incl;   // block total
}

// B: single block exclusive scan of 196 block sums; writes rowstart[NNODES]
__global__ void __launch_bounds__(256)
k_scan_block() {
    __shared__ int wsum[8];
    const int tid = threadIdx.x;
    const int lane = tid & 31;
    const int wrp = tid >> 5;

    int val = (tid < SCAN_BLOCKS) ? g_bsum[tid] : 0;
    int incl = val;
    #pragma unroll
    for (int off = 1; off < 32; off <<= 1) {
        int v = __shfl_up_sync(0xffffffffu, incl, off);
        if (lane >= off) incl += v;
    }
    if (lane == 31) wsum[wrp] = incl;
    __syncthreads();
    if (wrp == 0) {
        int s = (lane < 8) ? wsum[lane] : 0;
        #pragma unroll
        for (int off = 1; off < 8; off <<= 1) {
            int v = __shfl_up_sync(0xffffffffu, s, off);
            if (lane >= off) s += v;
        }
        if (lane < 8) wsum[lane] = s;
    }
    __syncthreads();
    const int warpOff = (wrp == 0) ? 0 : wsum[wrp - 1];
    if (tid < SCAN_BLOCKS) g_bsum[tid] = warpOff + incl - val;  // exclusive
    if (tid == 255) g_rowstart[NNODES] = wsum[7];               // grand total
}

// C: distribute offsets -> rowstart/cursor; self-clear g_deg (coalesced)
__global__ void __launch_bounds__(256)
k_scan_add() {
    const int i = blockIdx.x * 256 + threadIdx.x;
    if (i < NNODES) {
        const int rs = g_exloc[i] + g_bsum[blockIdx.x];
        g_rowstart[i] = rs;
        g_cursor[i] = rs;
        g_deg[i] = 0;
    }
}

__global__ void k_fill(const int4* __restrict__ edges2, int Epairs) {
    int i = blockIdx.x * blockDim.x + threadIdx.x;
    if (i < Epairs) {
        int4 e2 = edges2[i];
        int p0 = atomicAdd(&g_cursor[e2.y], 1);
        g_csr[p0] = e2.x;
        int p1 = atomicAdd(&g_cursor[e2.w], 1);
        g_csr[p1] = e2.z;
    }
}

// ---------------------------------------------------------------------------
// Packed f32x2 helpers (FFMA2 path — ptxas won't auto-fuse)
__device__ __forceinline__ unsigned long long pack2(float x, float y) {
    unsigned long long r;
    asm("mov.b64 %0, {%1, %2};" : "=l"(r) : "f"(x), "f"(y));
    return r;
}
__device__ __forceinline__ void unpack2(unsigned long long v, float& x, float& y) {
    asm("mov.b64 {%0, %1}, %2;" : "=f"(x), "=f"(y) : "l"(v));
}
__device__ __forceinline__ void fma2(unsigned long long& d,
                                     unsigned long long a,
                                     unsigned long long b) {
    asm("fma.rn.f32x2 %0, %1, %2, %0;" : "+l"(d) : "l"(a), "l"(b));
}

// ---------------------------------------------------------------------------
// Fused: aggregate 32 nodes x BOTH batches into smem (batch-packed float2),
// then GEMM(64x128x128)+bias+relu with batch-packed FFMA2 accumulators.
__global__ void __launch_bounds__(256, 3)
k_fused(const float* __restrict__ nodes,
        const float* __restrict__ weight,
        const float* __restrict__ bias,
        float* __restrict__ out) {
    __shared__ float2 As2[NODES_PB][FDIM];   // 32KB {batch0, batch1}
    __shared__ float Ws[32][FDIM];           // 16KB (one k-quarter of W)

    const int tid = threadIdx.x;
    const int w = tid >> 5;
    const int lane = tid & 31;
    const int node0 = blockIdx.x * NODES_PB;

    // ---- phase 1: aggregation (both batches) ----
    #pragma unroll 1
    for (int j = 0; j < 4; j++) {
        const int nl = w * 4 + j;            // local node 0..31
        const int n = node0 + nl;
        float4 acc0 = make_float4(0.f, 0.f, 0.f, 0.f);
        float4 acc1 = make_float4(0.f, 0.f, 0.f, 0.f);
        float scale = 0.0f;
        if (n < NNODES) {
            const int rs = g_rowstart[n];
            const int re = g_rowstart[n + 1];
            const float* nb0 = nodes + lane * 4;
            const float* nb1 = nodes + (size_t)NNODES * FDIM + lane * 4;
            int i = rs;
            for (; i + 2 <= re; i += 2) {
                int s0 = g_csr[i], s1 = g_csr[i + 1];
                float4 a = *(const float4*)(nb0 + (size_t)s0 * FDIM);
                float4 b = *(const float4*)(nb0 + (size_t)s1 * FDIM);
                float4 c = *(const float4*)(nb1 + (size_t)s0 * FDIM);
                float4 d = *(const float4*)(nb1 + (size_t)s1 * FDIM);
                acc0.x += a.x + b.x; acc0.y += a.y + b.y;
                acc0.z += a.z + b.z; acc0.w += a.w + b.w;
                acc1.x += c.x + d.x; acc1.y += c.y + d.y;
                acc1.z += c.z + d.z; acc1.w += c.w + d.w;
            }
            if (i < re) {
                int s0 = g_csr[i];
                float4 a = *(const float4*)(nb0 + (size_t)s0 * FDIM);
                float4 c = *(const float4*)(nb1 + (size_t)s0 * FDIM);
                acc0.x += a.x; acc0.y += a.y; acc0.z += a.z; acc0.w += a.w;
                acc1.x += c.x; acc1.y += c.y; acc1.z += c.z; acc1.w += c.w;
            }
            scale = 1.0f / (float)(re - rs + 1);
        }
        float4 lo = make_float4(acc0.x * scale, acc1.x * scale,
                                acc0.y * scale, acc1.y * scale);
        float4 hi = make_float4(acc0.z * scale, acc1.z * scale,
                                acc0.w * scale, acc1.w * scale);
        *(float4*)&As2[nl][lane * 4] = lo;
        *(float4*)&As2[nl][lane * 4 + 2] = hi;
    }

    // ---- phase 2: GEMM ----
    const int colg = tid & 31;    // cols 4*colg .. +4
    const int nodeg = tid >> 5;   // local nodes 4*nodeg .. +4

    const float4 b4 = *(const float4*)(bias + colg * 4);
    unsigned long long acc[4][4];   // [node][col], packed {b0,b1}
    #pragma unroll
    for (int j = 0; j < 4; j++) {
        acc[j][0] = pack2(b4.x, b4.x);
        acc[j][1] = pack2(b4.y, b4.y);
        acc[j][2] = pack2(b4.z, b4.z);
        acc[j][3] = pack2(b4.w, b4.w);
    }

    const float4* w4g = (const float4*)weight;
    #pragma unroll
    for (int kq = 0; kq < 4; kq++) {
        __syncthreads();   // kq=0: As2 ready; kq>0: prior Ws reads done
        #pragma unroll
        for (int i = 0; i < 4; i++)
            ((float4*)Ws)[tid + i * 256] = w4g[kq * 1024 + tid + i * 256];
        __syncthreads();

        #pragma unroll 4
        for (int k = 0; k < 32; k++) {
            const float4 wv = *(const float4*)&Ws[k][colg * 4];
            const unsigned long long w0 = pack2(wv.x, wv.x);
            const unsigned long long w1 = pack2(wv.y, wv.y);
            const unsigned long long w2 = pack2(wv.z, wv.z);
            const unsigned long long w3 = pack2(wv.w, wv.w);
            #pragma unroll
            for (int j = 0; j < 4; j++) {
                const unsigned long long ap =
                    *(const unsigned long long*)&As2[nodeg * 4 + j][kq * 32 + k];
                fma2(acc[j][0], w0, ap);
                fma2(acc[j][1], w1, ap);
                fma2(acc[j][2], w2, ap);
                fma2(acc[j][3], w3, ap);
            }
        }
    }

    // ---- store with relu (unpack batch lanes) ----
    #pragma unroll
    for (int j = 0; j < 4; j++) {
        const int n = node0 + nodeg * 4 + j;
        if (n < NNODES) {
            float x0, y0, x1, y1, x2, y2, x3, y3;
            unpack2(acc[j][0], x0, y0);
            unpack2(acc[j][1], x1, y1);
            unpack2(acc[j][2], x2, y2);
            unpack2(acc[j][3], x3, y3);
            float4 o0 = make_float4(fmaxf(x0, 0.f), fmaxf(x1, 0.f),
                                    fmaxf(x2, 0.f), fmaxf(x3, 0.f));
            float4 o1 = make_float4(fmaxf(y0, 0.f), fmaxf(y1, 0.f),
                                    fmaxf(y2, 0.f), fmaxf(y3, 0.f));
            *(float4*)(out + (size_t)n * FDIM + colg * 4) = o0;
            *(float4*)(out + (size_t)(NNODES + n) * FDIM + colg * 4) = o1;
        }
    }
}

// ---------------------------------------------------------------------------
extern "C" void kernel_launch(void* const* d_in, const int* in_sizes, int n_in,
                              void* d_out, int out_size) {
    const float* nodes = (const float*)d_in[0];
    const int4* edges2 = (const int4*)d_in[1];   // int32 [E,2], 2 edges per int4
    const float* weight = (const float*)d_in[2];
    const float* bias = (const float*)d_in[3];
    float* out = (float*)d_out;

    int E = in_sizes[1] / 2;
    if (E > EDGES_MAX) E = EDGES_MAX;
    int Epairs = E / 2;   // E is even

    k_hist<<<(Epairs + 255) / 256, 256>>>(edges2, Epairs);
    k_scan_local<<<SCAN_BLOCKS, 256>>>();
    k_scan_block<<<1, 256>>>();
    k_scan_add<<<SCAN_BLOCKS, 256>>>();
    k_fill<<<(Epairs + 255) / 256, 256>>>(edges2, Epairs);
    k_fused<<<NBLOCKS, 256>>>(nodes, weight, bias, out);
}